// round 11
// baseline (speedup 1.0000x reference)
#include <cuda_runtime.h>
#include <cstdint>

// DownscaleLabel: label [8,1024,1024] int32 in {-1,0..6} -> out [8,1,64,64] f32.
// Per 16x16 tile: 8-class histogram (ignore -1 -> class 7 via &7), first-max
// argmax, -1 if argmax==7 or max_count < 192 (== ratio < 0.75, exact).
//
// TMA-pipeline version. CTA = 256 threads = 8 warps, handles one tile-row of
// one image: 16 image rows x 1024 px = 64KB. Thread 0 queues 4 cp.async.bulk
// copies of 16KB (4 image rows each) into dynamic smem, one mbarrier per
// stage (expect_tx). Warps consume each stage from smem: warp w owns tiles
// 8w..8w+7 (512B per row); lane reads its int4 column (tile = lane>>2,
// quad = lane&3) -> contiguous conflict-free LDS.128. Histogram: nibble
// phases widened into byte accs e=(c0,c2,c4,c6), o=(c1,c3,c5,c7) (max 64);
// reduce xor1 (bytes), widen, xor2 (16-bit, max 256). Lanes quad==0 emit.

static constexpr int STAGE_BYTES = 16384;     // 4 image rows
static constexpr int N_STAGES = 4;
static constexpr int TILES_PER_IMG = 64 * 64; // 4096

__device__ __forceinline__ uint32_t smem_u32(const void* p) {
    return (uint32_t)__cvta_generic_to_shared(p);
}

__device__ __forceinline__ void mbar_wait(uint32_t mbar, uint32_t parity) {
    uint32_t done;
    do {
        asm volatile(
            "{\n\t.reg .pred p;\n\t"
            "mbarrier.try_wait.parity.acquire.cta.shared::cta.b64 p, [%1], %2, 0x989680;\n\t"
            "selp.b32 %0, 1, 0, p;\n\t}"
            : "=r"(done) : "r"(mbar), "r"(parity) : "memory");
    } while (!done);
}

__global__ void __launch_bounds__(256)
downscale_label_kernel(const int* __restrict__ label,
                       float* __restrict__ out) {
    extern __shared__ char smem[];                       // 64KB data
    __shared__ alignas(8) unsigned long long mbar[N_STAGES];

    const int tid  = threadIdx.x;
    const int wid  = tid >> 5;
    const int lane = tid & 31;

    const int bx = blockIdx.x;           // 0..511
    const int b  = bx >> 6;              // image
    const int th = bx & 63;              // tile row

    // Init stage barriers, make them visible to the async proxy.
    if (tid == 0) {
#pragma unroll
        for (int s = 0; s < N_STAGES; ++s) {
            asm volatile("mbarrier.init.shared.b64 [%0], 1;"
                         :: "r"(smem_u32(&mbar[s])) : "memory");
        }
        asm volatile("fence.proxy.async.shared::cta;" ::: "memory");
    }
    __syncthreads();

    // Queue all 4 bulk copies (64KB total) immediately: zero data registers,
    // MLP lives in the TMA engine queues.
    if (tid == 0) {
        const char* src = reinterpret_cast<const char*>(label)
                          + ((size_t)b << 22)            // b * 1M px * 4B
                          + ((size_t)th << 16);          // th * 16 rows * 4KB
#pragma unroll
        for (int s = 0; s < N_STAGES; ++s) {
            const uint32_t mb = smem_u32(&mbar[s]);
            asm volatile(
                "mbarrier.arrive.expect_tx.shared.b64 _, [%0], %1;"
                :: "r"(mb), "r"((uint32_t)STAGE_BYTES) : "memory");
            asm volatile(
                "cp.async.bulk.shared::cluster.global.mbarrier::complete_tx::bytes "
                "[%0], [%1], %2, [%3];"
                :: "r"(smem_u32(smem) + s * STAGE_BYTES),
                   "l"(src + s * STAGE_BYTES),
                   "r"((uint32_t)STAGE_BYTES), "r"(mb)
                : "memory");
        }
    }

    // Byte histograms: e = classes (0,2,4,6), o = (1,3,5,7). Max 64/byte.
    unsigned e = 0u, o = 0u;

#define HPHASE(a, c)                                            \
    {                                                           \
        unsigned n = 0u;                                        \
        n += 1u << (((unsigned)(a).x & 7u) << 2);               \
        n += 1u << (((unsigned)(a).y & 7u) << 2);               \
        n += 1u << (((unsigned)(a).z & 7u) << 2);               \
        n += 1u << (((unsigned)(a).w & 7u) << 2);               \
        n += 1u << (((unsigned)(c).x & 7u) << 2);               \
        n += 1u << (((unsigned)(c).y & 7u) << 2);               \
        n += 1u << (((unsigned)(c).z & 7u) << 2);               \
        n += 1u << (((unsigned)(c).w & 7u) << 2);               \
        e += n & 0x0F0F0F0Fu;                                   \
        o += (n >> 4) & 0x0F0F0F0Fu;                            \
    }

    // Warp w owns the 512B column band [w*512, w*512+512) of every row.
    const int band = wid * 512 + lane * 16;

#pragma unroll
    for (int s = 0; s < N_STAGES; ++s) {
        mbar_wait(smem_u32(&mbar[s]), 0);
        const char* st = smem + s * STAGE_BYTES;
        // 4 image rows per stage, each row 4KB.
        const int4 a0 = *reinterpret_cast<const int4*>(st + 0 * 4096 + band);
        const int4 a1 = *reinterpret_cast<const int4*>(st + 1 * 4096 + band);
        const int4 a2 = *reinterpret_cast<const int4*>(st + 2 * 4096 + band);
        const int4 a3 = *reinterpret_cast<const int4*>(st + 3 * 4096 + band);
        HPHASE(a0, a1)
        HPHASE(a2, a3)
    }
#undef HPHASE

    // Reduce over the 4 quad lanes of each tile.
    e += __shfl_xor_sync(0xffffffffu, e, 1);   // max 128, bytes still safe
    o += __shfl_xor_sync(0xffffffffu, o, 1);
    unsigned e_lo = e & 0x00FF00FFu;           // [c0 | c4<<16]
    unsigned e_hi = (e >> 8) & 0x00FF00FFu;    // [c2 | c6<<16]
    unsigned o_lo = o & 0x00FF00FFu;           // [c1 | c5<<16]
    unsigned o_hi = (o >> 8) & 0x00FF00FFu;    // [c3 | c7<<16]
    e_lo += __shfl_xor_sync(0xffffffffu, e_lo, 2);
    e_hi += __shfl_xor_sync(0xffffffffu, e_hi, 2);
    o_lo += __shfl_xor_sync(0xffffffffu, o_lo, 2);
    o_hi += __shfl_xor_sync(0xffffffffu, o_hi, 2);

    if ((lane & 3) == 0) {
        int counts[8];
        counts[0] = e_lo & 0xFFFF;  counts[4] = e_lo >> 16;
        counts[2] = e_hi & 0xFFFF;  counts[6] = e_hi >> 16;
        counts[1] = o_lo & 0xFFFF;  counts[5] = o_lo >> 16;
        counts[3] = o_hi & 0xFFFF;  counts[7] = o_hi >> 16;

        int best = counts[0], arg = 0;
#pragma unroll
        for (int i = 1; i < 8; ++i) {
            if (counts[i] > best) { best = counts[i]; arg = i; }  // first-max
        }
        // ratio < 0.75  <=>  count < 192 (0.75 * 256 == 192 exactly)
        const int res = (arg == 7 || best < 192) ? -1 : arg;

        const int tw = (wid << 3) + (lane >> 2);
        out[b * TILES_PER_IMG + th * 64 + tw] = (float)res;
    }
}

extern "C" void kernel_launch(void* const* d_in, const int* in_sizes, int n_in,
                              void* d_out, int out_size) {
    const int* label = (const int*)d_in[0];
    float* out = (float*)d_out;

    const int smem_bytes = N_STAGES * STAGE_BYTES;  // 64KB
    cudaFuncSetAttribute(downscale_label_kernel,
                         cudaFuncAttributeMaxDynamicSharedMemorySize,
                         smem_bytes);

    // pixels per CTA = 16 rows * 1024 = 16384 -> 512 CTAs for 8 images.
    const int blocks = in_sizes[0] / 16384;

    downscale_label_kernel<<<blocks, 256, smem_bytes>>>(label, out);
}

// round 12
// speedup vs baseline: 1.2724x; 1.2724x over previous
#include <cuda_runtime.h>
#include <cstdint>

// DownscaleLabel: label [8,1024,1024] int32 in {-1,0..6} -> out [8,1,64,64] f32.
// Per 16x16 tile: 8-class histogram (ignore -1 -> class 7 via &7), first-max
// argmax, -1 if argmax==7 or max_count < 192 (== ratio < 0.75, exact).
//
// 1 warp = 4 horizontally-adjacent tiles, 8 lanes/tile:
//   tile = lane>>3, sub = lane&7, quad = sub&3 (int4 col), rows (sub>>2)*8..+7.
// 8 front-batched int4 loads per thread (32 data regs co-live, true MLP=8),
// allowed by __launch_bounds__(256,4) (<=64 regs). 8192 warps total.
// Histogram: nibble phases (max 8/field) widened into byte accs
// e=(c0,c2,c4,c6), o=(c1,c3,c5,c7), max 32/byte. Reduce over 8 sub-lanes:
// xor1, xor2 in bytes (max 128), widen to 16-bit fields, xor4 (max 256).

static constexpr int SCALE = 16;
static constexpr int TILES_PER_IMG = 64 * 64;            // 4096
static constexpr int WARPS_PER_IMG = TILES_PER_IMG / 4;  // 1024

__global__ void __launch_bounds__(256, 4)
downscale_label_kernel(const int* __restrict__ label,
                       float* __restrict__ out,
                       int n_warps) {
    const int wg   = (blockIdx.x * blockDim.x + threadIdx.x) >> 5;
    const int lane = threadIdx.x & 31;
    if (wg >= n_warps) return;

    const int b   = wg >> 10;                   // / WARPS_PER_IMG (1024)
    const int wi  = wg & (WARPS_PER_IMG - 1);
    const int th  = wi >> 4;                    // tile row (64), 16 warps/row
    const int twg = wi & 15;                    // group of 4 tiles

    const int tile = lane >> 3;                 // 0..3
    const int sub  = lane & 7;
    const int quad = sub & 3;                   // int4 within 64B tile row
    const int row0 = (sub >> 2) * 8;            // 0 or 8

    // int4 index: image row = 256 int4. Tile col px = (twg*4+tile)*16.
    const int4* p = reinterpret_cast<const int4*>(label)
                    + ((size_t)b << 18)                    // b * 1M px / 4
                    + ((size_t)(th * 16 + row0) << 8)      // row * 256
                    + ((twg << 4) + (tile << 2) + quad);

    // Front-batch all 8 loads (32 data regs) -> true MLP = 8.
    const int4 v0 = __ldg(p);
    const int4 v1 = __ldg(p + 1 * 256);
    const int4 v2 = __ldg(p + 2 * 256);
    const int4 v3 = __ldg(p + 3 * 256);
    const int4 v4 = __ldg(p + 4 * 256);
    const int4 v5 = __ldg(p + 5 * 256);
    const int4 v6 = __ldg(p + 6 * 256);
    const int4 v7 = __ldg(p + 7 * 256);

    // Byte histograms: e = classes (0,2,4,6), o = (1,3,5,7). Max 32/byte.
    unsigned e = 0u, o = 0u;

#define HPHASE(a, c)                                            \
    {                                                           \
        unsigned n = 0u;                                        \
        n += 1u << (((unsigned)(a).x & 7u) << 2);               \
        n += 1u << (((unsigned)(a).y & 7u) << 2);               \
        n += 1u << (((unsigned)(a).z & 7u) << 2);               \
        n += 1u << (((unsigned)(a).w & 7u) << 2);               \
        n += 1u << (((unsigned)(c).x & 7u) << 2);               \
        n += 1u << (((unsigned)(c).y & 7u) << 2);               \
        n += 1u << (((unsigned)(c).z & 7u) << 2);               \
        n += 1u << (((unsigned)(c).w & 7u) << 2);               \
        e += n & 0x0F0F0F0Fu;                                   \
        o += (n >> 4) & 0x0F0F0F0Fu;                            \
    }

    HPHASE(v0, v1)
    HPHASE(v2, v3)
    HPHASE(v4, v5)
    HPHASE(v6, v7)
#undef HPHASE

    // Reduce over the 8 sub-lanes of each tile (bytes safe to 128).
    e += __shfl_xor_sync(0xffffffffu, e, 1);   // max 64
    o += __shfl_xor_sync(0xffffffffu, o, 1);
    e += __shfl_xor_sync(0xffffffffu, e, 2);   // max 128
    o += __shfl_xor_sync(0xffffffffu, o, 2);
    // Widen byte fields -> 16-bit fields for the final (max 256) round.
    unsigned e_lo = e & 0x00FF00FFu;           // [c0 | c4<<16]
    unsigned e_hi = (e >> 8) & 0x00FF00FFu;    // [c2 | c6<<16]
    unsigned o_lo = o & 0x00FF00FFu;           // [c1 | c5<<16]
    unsigned o_hi = (o >> 8) & 0x00FF00FFu;    // [c3 | c7<<16]
    e_lo += __shfl_xor_sync(0xffffffffu, e_lo, 4);
    e_hi += __shfl_xor_sync(0xffffffffu, e_hi, 4);
    o_lo += __shfl_xor_sync(0xffffffffu, o_lo, 4);
    o_hi += __shfl_xor_sync(0xffffffffu, o_hi, 4);

    if (sub == 0) {
        int counts[8];
        counts[0] = e_lo & 0xFFFF;  counts[4] = e_lo >> 16;
        counts[2] = e_hi & 0xFFFF;  counts[6] = e_hi >> 16;
        counts[1] = o_lo & 0xFFFF;  counts[5] = o_lo >> 16;
        counts[3] = o_hi & 0xFFFF;  counts[7] = o_hi >> 16;

        int best = counts[0], arg = 0;
#pragma unroll
        for (int i = 1; i < 8; ++i) {
            if (counts[i] > best) { best = counts[i]; arg = i; }  // first-max
        }
        // ratio < 0.75  <=>  count < 192 (0.75 * 256 == 192 exactly)
        const int res = (arg == 7 || best < 192) ? -1 : arg;

        const int tw = (twg << 2) + tile;
        out[b * TILES_PER_IMG + th * 64 + tw] = (float)res;
    }
}

extern "C" void kernel_launch(void* const* d_in, const int* in_sizes, int n_in,
                              void* d_out, int out_size) {
    const int* label = (const int*)d_in[0];
    float* out = (float*)d_out;

    // 8M px / 256 px per tile / 4 tiles per warp = 8192 warps.
    const int n_tiles = in_sizes[0] / (SCALE * SCALE);
    const int n_warps = n_tiles / 4;

    const int threads = 256;                 // 8 warps/block -> 1024 blocks
    const int blocks = (n_warps * 32 + threads - 1) / threads;

    downscale_label_kernel<<<blocks, threads>>>(label, out, n_warps);
}